// round 3
// baseline (speedup 1.0000x reference)
#include <cuda_runtime.h>
#include <cuda_bf16.h>

#define D 128
#define MAXN 50176   // padded N (multiple of 64)

// ---------------- scratch (device globals, no allocation) ----------------
__device__ float g_x[MAXN * D];
__device__ float g_h[MAXN * D];
__device__ float g_agg[MAXN * D];
__device__ float g_onorm[MAXN];
__device__ float g_inorm[MAXN];
__device__ float g_colsum[D];
__device__ float g_colsq[D];
__device__ float g_scale[D];
__device__ float g_shift[D];

// ---------------- f32x2 helpers ----------------
__device__ __forceinline__ unsigned long long pack2(float x, float y) {
    unsigned long long r;
    asm("mov.b64 %0, {%1, %2};" : "=l"(r) : "f"(x), "f"(y));
    return r;
}
__device__ __forceinline__ void ffma2(unsigned long long& d,
                                      unsigned long long a,
                                      unsigned long long b) {
    asm("fma.rn.f32x2 %0, %1, %2, %0;" : "+l"(d) : "l"(a), "l"(b));
}
__device__ __forceinline__ float2 unpack2(unsigned long long v) {
    float2 r;
    asm("mov.b64 {%0, %1}, %2;" : "=f"(r.x), "=f"(r.y) : "l"(v));
    return r;
}

// ---------------- small prep kernels ----------------
__global__ void zero_norms_kernel(int N) {
    int i = blockIdx.x * blockDim.x + threadIdx.x;
    if (i < N) { g_onorm[i] = 0.f; g_inorm[i] = 0.f; }
}

__global__ void deg_kernel(const int* __restrict__ src,
                           const int* __restrict__ dst, int E) {
    int e = blockIdx.x * blockDim.x + threadIdx.x;
    if (e < E) {
        atomicAdd(&g_onorm[src[e]], 1.0f);
        atomicAdd(&g_inorm[dst[e]], 1.0f);
    }
}

__global__ void finalize_norms_kernel(int N) {
    int i = blockIdx.x * blockDim.x + threadIdx.x;
    if (i < N) {
        float a = g_onorm[i];
        float b = g_inorm[i];
        g_onorm[i] = (a > 0.f) ? rsqrtf(a) : 0.f;
        g_inorm[i] = (b > 0.f) ? rsqrtf(b) : 0.f;
    }
}

__global__ void gather_kernel(const int* __restrict__ node_ids,
                              const float* __restrict__ emb, int N) {
    int gid = blockIdx.x * blockDim.x + threadIdx.x;
    if (gid < N * 32) {
        int i = gid >> 5;
        int c = gid & 31;
        ((float4*)g_x)[gid] = ((const float4*)emb)[node_ids[i] * 32 + c];
    }
}

__global__ void zero_agg_kernel(int N) {
    int total = N * 32;  // float4 count
    float4 z = make_float4(0.f, 0.f, 0.f, 0.f);
    for (int idx = blockIdx.x * blockDim.x + threadIdx.x; idx < total;
         idx += gridDim.x * blockDim.x) {
        ((float4*)g_agg)[idx] = z;
        if (idx < 32) {
            ((float4*)g_colsum)[idx] = z;
            ((float4*)g_colsq)[idx] = z;
        }
    }
}

// ---------------- edge scatter: warp per edge, vector RED ----------------
__global__ void scatter_kernel(const int* __restrict__ src,
                               const int* __restrict__ dst, int E) {
    int gid = blockIdx.x * blockDim.x + threadIdx.x;
    int e = gid >> 5;
    if (e >= E) return;
    int lane = gid & 31;
    int s = src[e];
    int d = dst[e];
    float ns = g_onorm[s];
    float4 v = ((const float4*)g_x)[s * 32 + lane];
    float* p = g_agg + d * D + lane * 4;
    asm volatile("red.global.add.v4.f32 [%0], {%1, %2, %3, %4};"
                 :: "l"(p), "f"(v.x * ns), "f"(v.y * ns),
                    "f"(v.z * ns), "f"(v.w * ns)
                 : "memory");
}

// ---------------- fused dual GEMM + bias + relu + residual ----------------
// h = relu((agg * inorm) @ W + b) + relu(x @ Rw + Rb)
// Block: 64 rows. Warps 0-3 -> W branch, warps 4-7 -> Rw branch.
// Each of the 128 threads per branch owns an 8x8 output tile, accumulated
// as f32x2 packed over column pairs.
#define AS_STRIDE 132
#define SMEM_FLOATS (16384 + 16384 + 2 * 64 * AS_STRIDE + 256)
#define SMEM_BYTES (SMEM_FLOATS * 4)

__global__ __launch_bounds__(256, 1)
void gemm_kernel(const float* __restrict__ W, const float* __restrict__ R,
                 const float* __restrict__ b, const float* __restrict__ rb,
                 int N) {
    extern __shared__ float sm[];
    float* Wsm  = sm;                       // 16384
    float* Rsm  = sm + 16384;               // 16384
    float* As   = sm + 32768;               // 64*132 = 8448
    float* Xs   = As + 64 * AS_STRIDE;      // 8448
    float* bsm  = Xs + 64 * AS_STRIDE;      // 128
    float* rbsm = bsm + 128;                // 128

    const int tid = threadIdx.x;
    const int rowbase = blockIdx.x * 64;

    // load weights
    for (int idx = tid; idx < 4096; idx += 256) {
        ((float4*)Wsm)[idx] = ((const float4*)W)[idx];
        ((float4*)Rsm)[idx] = ((const float4*)R)[idx];
    }
    if (tid < 128) { bsm[tid] = b[tid]; rbsm[tid] = rb[tid]; }

    // load input tiles (agg pre-scaled by inorm)
    for (int idx = tid; idx < 2048; idx += 256) {
        int r = idx >> 5;
        int c4 = idx & 31;
        int row = rowbase + r;
        float4 va = make_float4(0.f, 0.f, 0.f, 0.f);
        float4 vx = va;
        if (row < N) {
            float inn = g_inorm[row];
            float4 ag = ((const float4*)g_agg)[row * 32 + c4];
            va = make_float4(ag.x * inn, ag.y * inn, ag.z * inn, ag.w * inn);
            vx = ((const float4*)g_x)[row * 32 + c4];
        }
        *(float4*)(As + r * AS_STRIDE + c4 * 4) = va;
        *(float4*)(Xs + r * AS_STRIDE + c4 * 4) = vx;
    }
    __syncthreads();

    const int h = tid & 127;
    const bool first = (tid < 128);
    const float* Mt = first ? As : Xs;
    const float* Wt = first ? Wsm : Rsm;
    const int cg = h & 15;      // column group: cols [cg*8, cg*8+8)
    const int rg = h >> 4;      // row group:    rows [rg*8, rg*8+8)
    const float* mrow = Mt + rg * 8 * AS_STRIDE;
    const float* wcol = Wt + cg * 8;

    unsigned long long acc[8][4];
#pragma unroll
    for (int i = 0; i < 8; i++)
#pragma unroll
        for (int j = 0; j < 4; j++) acc[i][j] = 0ull;

#pragma unroll 4
    for (int k = 0; k < 128; ++k) {
        ulonglong2 wA = *(const ulonglong2*)(wcol + k * 128);
        ulonglong2 wB = *(const ulonglong2*)(wcol + k * 128 + 4);
#pragma unroll
        for (int i = 0; i < 8; i++) {
            float a = mrow[i * AS_STRIDE + k];
            unsigned long long ad = pack2(a, a);
            ffma2(acc[i][0], ad, wA.x);
            ffma2(acc[i][1], ad, wA.y);
            ffma2(acc[i][2], ad, wB.x);
            ffma2(acc[i][3], ad, wB.y);
        }
    }

    float* Hs = As;  // reuse As region: each W-branch warp only rewrites rows
                     // it alone read (warp w covers rows [w*16, w*16+16)).
    if (first) {
#pragma unroll
        for (int i = 0; i < 8; i++) {
            int rl = rg * 8 + i;
#pragma unroll
            for (int j = 0; j < 4; j++) {
                float2 v = unpack2(acc[i][j]);
                int col = cg * 8 + 2 * j;
                v.x = fmaxf(v.x + bsm[col], 0.f);
                v.y = fmaxf(v.y + bsm[col + 1], 0.f);
                *(float2*)(Hs + rl * AS_STRIDE + col) = v;
            }
        }
    }
    __syncthreads();
    if (!first) {
#pragma unroll
        for (int i = 0; i < 8; i++) {
            int rl = rg * 8 + i;
            int row = rowbase + rl;
            if (row < N) {
#pragma unroll
                for (int j = 0; j < 4; j++) {
                    float2 v = unpack2(acc[i][j]);
                    int col = cg * 8 + 2 * j;
                    v.x = fmaxf(v.x + rbsm[col], 0.f) + Hs[rl * AS_STRIDE + col];
                    v.y = fmaxf(v.y + rbsm[col + 1], 0.f) + Hs[rl * AS_STRIDE + col + 1];
                    *(float2*)(g_h + row * D + col) = v;
                }
            }
        }
    }
}

// ---------------- BN statistics ----------------
__global__ void reduce_kernel(int N) {
    int c = threadIdx.x;  // 128 threads, one per column
    int r0 = blockIdx.x * 256;
    int r1 = min(r0 + 256, N);
    float s = 0.f, s2 = 0.f;
    for (int r = r0; r < r1; ++r) {
        float v = g_h[r * D + c];
        s += v;
        s2 += v * v;
    }
    atomicAdd(&g_colsum[c], s);
    atomicAdd(&g_colsq[c], s2);
}

__global__ void stats_kernel(const float* __restrict__ gamma,
                             const float* __restrict__ beta, int N) {
    int t = threadIdx.x;
    float invN = 1.0f / (float)N;
    float mu = g_colsum[t] * invN;
    float var = g_colsq[t] * invN - mu * mu;
    var = fmaxf(var, 0.f);
    float istd = rsqrtf(var + 1e-5f);
    float sc = gamma[t] * istd;
    g_scale[t] = sc;
    g_shift[t] = beta[t] - mu * sc;
}

__global__ void normalize_kernel(int N, int is_final, float* __restrict__ out) {
    int total = N * 32;
    float* o = is_final ? out : g_x;
    for (int idx = blockIdx.x * blockDim.x + threadIdx.x; idx < total;
         idx += gridDim.x * blockDim.x) {
        int c4 = idx & 31;
        float4 v = ((const float4*)g_h)[idx];
        float4 s = ((const float4*)g_scale)[c4];
        float4 sh = ((const float4*)g_shift)[c4];
        float4 r;
        r.x = v.x * s.x + sh.x;
        r.y = v.y * s.y + sh.y;
        r.z = v.z * s.z + sh.z;
        r.w = v.w * s.w + sh.w;
        ((float4*)o)[idx] = r;
    }
}

// ---------------- launch ----------------
extern "C" void kernel_launch(void* const* d_in, const int* in_sizes, int n_in,
                              void* d_out, int out_size) {
    const int*   node_ids = (const int*)d_in[0];
    const int*   src      = (const int*)d_in[1];
    const int*   dst      = (const int*)d_in[2];
    const float* emb      = (const float*)d_in[3];
    const float* Ws       = (const float*)d_in[4];
    const float* bs       = (const float*)d_in[5];
    const float* Rws      = (const float*)d_in[6];
    const float* Rbs      = (const float*)d_in[7];
    const float* gammas   = (const float*)d_in[8];
    const float* betas    = (const float*)d_in[9];

    const int N = in_sizes[0];
    const int E = in_sizes[1];
    const int L = in_sizes[4] / (D * D);

    cudaFuncSetAttribute(gemm_kernel,
                         cudaFuncAttributeMaxDynamicSharedMemorySize,
                         SMEM_BYTES);

    zero_norms_kernel<<<(N + 255) / 256, 256>>>(N);
    deg_kernel<<<(E + 255) / 256, 256>>>(src, dst, E);
    finalize_norms_kernel<<<(N + 255) / 256, 256>>>(N);
    gather_kernel<<<(N * 32 + 255) / 256, 256>>>(node_ids, emb, N);

    for (int l = 0; l < L; ++l) {
        zero_agg_kernel<<<512, 256>>>(N);
        scatter_kernel<<<(E * 32 + 255) / 256, 256>>>(src, dst, E);
        gemm_kernel<<<(N + 63) / 64, 256, SMEM_BYTES>>>(
            Ws + l * D * D, Rws + l * D * D, bs + l * D, Rbs + l * D, N);
        reduce_kernel<<<(N + 255) / 256, 128>>>(N);
        stats_kernel<<<1, 128>>>(gammas + l * D, betas + l * D, N);
        normalize_kernel<<<512, 256>>>(N, (l == L - 1) ? 1 : 0, (float*)d_out);
    }
}

// round 4
// speedup vs baseline: 1.1713x; 1.1713x over previous
#include <cuda_runtime.h>
#include <cuda_bf16.h>

#define D 128
#define MAXN 50176    // padded N (multiple of 64)
#define MAXE 524288

// ---------------- scratch (device globals, no allocation) ----------------
__device__ float g_x[MAXN * D];
__device__ float g_h[MAXN * D];
__device__ float g_agg[MAXN * D];
__device__ float g_onorm[MAXN];
__device__ float g_inorm[MAXN];
__device__ float g_colsum[D];
__device__ float g_colsq[D];
__device__ float g_scale[D];
__device__ float g_shift[D];

// CSR structures
__device__ int   g_outdeg[MAXN];
__device__ int   g_indeg[MAXN];
__device__ int   g_rowptr[MAXN + 1];
__device__ int   g_cursor[MAXN];
__device__ int   g_chunksum[256];
__device__ int   g_chunkoff[256];
__device__ int   g_esrc[MAXE];
__device__ float g_ew[MAXE];

// ---------------- f32x2 helpers ----------------
__device__ __forceinline__ unsigned long long pack2(float x, float y) {
    unsigned long long r;
    asm("mov.b64 %0, {%1, %2};" : "=l"(r) : "f"(x), "f"(y));
    return r;
}
__device__ __forceinline__ void ffma2(unsigned long long& d,
                                      unsigned long long a,
                                      unsigned long long b) {
    asm("fma.rn.f32x2 %0, %1, %2, %0;" : "+l"(d) : "l"(a), "l"(b));
}
__device__ __forceinline__ float2 unpack2(unsigned long long v) {
    float2 r;
    asm("mov.b64 {%0, %1}, %2;" : "=f"(r.x), "=f"(r.y) : "l"(v));
    return r;
}

// ---------------- prep: degrees + norms ----------------
__global__ void zero_deg_kernel(int N) {
    int i = blockIdx.x * blockDim.x + threadIdx.x;
    if (i < N) { g_outdeg[i] = 0; g_indeg[i] = 0; }
}

__global__ void deg_kernel(const int* __restrict__ src,
                           const int* __restrict__ dst, int E) {
    int e = blockIdx.x * blockDim.x + threadIdx.x;
    if (e < E) {
        atomicAdd(&g_outdeg[src[e]], 1);
        atomicAdd(&g_indeg[dst[e]], 1);
    }
}

__global__ void finalize_norms_kernel(int N) {
    int i = blockIdx.x * blockDim.x + threadIdx.x;
    if (i < N) {
        int a = g_outdeg[i];
        int b = g_indeg[i];
        g_onorm[i] = (a > 0) ? rsqrtf((float)a) : 0.f;
        g_inorm[i] = (b > 0) ? rsqrtf((float)b) : 0.f;
    }
}

// ---------------- prep: exclusive scan of indeg -> rowptr ----------------
__global__ void scan1_kernel(int N) {
    __shared__ int sd[256];
    int i = blockIdx.x * 256 + threadIdx.x;
    sd[threadIdx.x] = (i < N) ? g_indeg[i] : 0;
    __syncthreads();
    for (int s = 128; s > 0; s >>= 1) {
        if (threadIdx.x < s) sd[threadIdx.x] += sd[threadIdx.x + s];
        __syncthreads();
    }
    if (threadIdx.x == 0) g_chunksum[blockIdx.x] = sd[0];
}

__global__ void scan2_kernel(int nch) {
    __shared__ int sd[256];
    int t = threadIdx.x;
    int v = (t < nch) ? g_chunksum[t] : 0;
    sd[t] = v;
    __syncthreads();
    for (int off = 1; off < 256; off <<= 1) {
        int val = (t >= off) ? sd[t - off] : 0;
        __syncthreads();
        sd[t] += val;
        __syncthreads();
    }
    if (t < nch) g_chunkoff[t] = sd[t] - v;  // exclusive
}

__global__ void scan3_kernel(int N, int E) {
    __shared__ int sd[256];
    int t = threadIdx.x;
    int i = blockIdx.x * 256 + t;
    int v = (i < N) ? g_indeg[i] : 0;
    sd[t] = v;
    __syncthreads();
    for (int off = 1; off < 256; off <<= 1) {
        int val = (t >= off) ? sd[t - off] : 0;
        __syncthreads();
        sd[t] += val;
        __syncthreads();
    }
    if (i < N) {
        int rp = g_chunkoff[blockIdx.x] + sd[t] - v;  // exclusive
        g_rowptr[i] = rp;
        g_cursor[i] = rp;
    }
    if (i == 0) g_rowptr[N] = E;
}

__global__ void fill_kernel(const int* __restrict__ src,
                            const int* __restrict__ dst, int E) {
    int e = blockIdx.x * blockDim.x + threadIdx.x;
    if (e < E) {
        int s = src[e];
        int d = dst[e];
        int p = atomicAdd(&g_cursor[d], 1);
        g_esrc[p] = s;
        g_ew[p] = g_onorm[s];
    }
}

// ---------------- embedding gather ----------------
__global__ void gather_kernel(const int* __restrict__ node_ids,
                              const float* __restrict__ emb, int N) {
    int gid = blockIdx.x * blockDim.x + threadIdx.x;
    if (gid < N * 32) {
        int i = gid >> 5;
        int c = gid & 31;
        ((float4*)g_x)[gid] = ((const float4*)emb)[node_ids[i] * 32 + c];
    }
}

// ---------------- CSR gather aggregation: warp per dst row ----------------
// agg[d] = inorm[d] * sum_{e: dst(e)=d} onorm[src(e)] * x[src(e)]
// No atomics, full row writes (no zeroing needed). Also zeroes BN stats.
__global__ void gather_agg_kernel(int N) {
    int gid = blockIdx.x * blockDim.x + threadIdx.x;
    int w = gid >> 5;
    int lane = gid & 31;
    if (blockIdx.x == 0 && threadIdx.x < 128) {
        g_colsum[threadIdx.x] = 0.f;
        g_colsq[threadIdx.x] = 0.f;
    }
    if (w >= N) return;
    int beg = g_rowptr[w];
    int end = g_rowptr[w + 1];
    float4 acc = make_float4(0.f, 0.f, 0.f, 0.f);
#pragma unroll 4
    for (int j = beg; j < end; ++j) {
        int s = g_esrc[j];
        float wt = g_ew[j];
        float4 v = ((const float4*)g_x)[s * 32 + lane];
        acc.x += wt * v.x;
        acc.y += wt * v.y;
        acc.z += wt * v.z;
        acc.w += wt * v.w;
    }
    float inn = g_inorm[w];
    acc.x *= inn; acc.y *= inn; acc.z *= inn; acc.w *= inn;
    ((float4*)g_agg)[w * 32 + lane] = acc;
}

// ---------------- fused dual GEMM + bias + relu + residual + BN stats ----
// h = relu(agg @ W + b) + relu(x @ Rw + Rb); also accumulates column
// sum / sum-of-squares of h into g_colsum / g_colsq.
#define AS_STRIDE 132
#define SMEM_FLOATS (16384 + 16384 + 2 * 64 * AS_STRIDE + 256 + 256)
#define SMEM_BYTES (SMEM_FLOATS * 4)

__global__ __launch_bounds__(256, 1)
void gemm_kernel(const float* __restrict__ W, const float* __restrict__ R,
                 const float* __restrict__ b, const float* __restrict__ rb,
                 int N) {
    extern __shared__ float sm[];
    float* Wsm  = sm;                       // 16384
    float* Rsm  = sm + 16384;               // 16384
    float* As   = sm + 32768;               // 64*132 = 8448
    float* Xs   = As + 64 * AS_STRIDE;      // 8448
    float* bsm  = Xs + 64 * AS_STRIDE;      // 128
    float* rbsm = bsm + 128;                // 128
    float* scs  = rbsm + 128;               // 128 col sums
    float* scq  = scs + 128;                // 128 col sq-sums

    const int tid = threadIdx.x;
    const int rowbase = blockIdx.x * 64;

    // load weights
    for (int idx = tid; idx < 4096; idx += 256) {
        ((float4*)Wsm)[idx] = ((const float4*)W)[idx];
        ((float4*)Rsm)[idx] = ((const float4*)R)[idx];
    }
    if (tid < 128) {
        bsm[tid] = b[tid];
        rbsm[tid] = rb[tid];
        scs[tid] = 0.f;
        scq[tid] = 0.f;
    }

    // load input tiles
    for (int idx = tid; idx < 2048; idx += 256) {
        int r = idx >> 5;
        int c4 = idx & 31;
        int row = rowbase + r;
        float4 va = make_float4(0.f, 0.f, 0.f, 0.f);
        float4 vx = va;
        if (row < N) {
            va = ((const float4*)g_agg)[row * 32 + c4];
            vx = ((const float4*)g_x)[row * 32 + c4];
        }
        *(float4*)(As + r * AS_STRIDE + c4 * 4) = va;
        *(float4*)(Xs + r * AS_STRIDE + c4 * 4) = vx;
    }
    __syncthreads();

    const int h = tid & 127;
    const bool first = (tid < 128);
    const float* Mt = first ? As : Xs;
    const float* Wt = first ? Wsm : Rsm;
    const int cg = h & 15;      // column group: cols [cg*8, cg*8+8)
    const int rg = h >> 4;      // row group:    rows [rg*8, rg*8+8)
    const float* mrow = Mt + rg * 8 * AS_STRIDE;
    const float* wcol = Wt + cg * 8;

    unsigned long long acc[8][4];
#pragma unroll
    for (int i = 0; i < 8; i++)
#pragma unroll
        for (int j = 0; j < 4; j++) acc[i][j] = 0ull;

#pragma unroll 4
    for (int k = 0; k < 128; ++k) {
        ulonglong2 wA = *(const ulonglong2*)(wcol + k * 128);
        ulonglong2 wB = *(const ulonglong2*)(wcol + k * 128 + 4);
#pragma unroll
        for (int i = 0; i < 8; i++) {
            float a = mrow[i * AS_STRIDE + k];
            unsigned long long ad = pack2(a, a);
            ffma2(acc[i][0], ad, wA.x);
            ffma2(acc[i][1], ad, wA.y);
            ffma2(acc[i][2], ad, wB.x);
            ffma2(acc[i][3], ad, wB.y);
        }
    }

    float* Hs = As;  // reuse As: each W-branch warp rewrites only rows it read
    if (first) {
#pragma unroll
        for (int i = 0; i < 8; i++) {
            int rl = rg * 8 + i;
#pragma unroll
            for (int j = 0; j < 4; j++) {
                float2 v = unpack2(acc[i][j]);
                int col = cg * 8 + 2 * j;
                v.x = fmaxf(v.x + bsm[col], 0.f);
                v.y = fmaxf(v.y + bsm[col + 1], 0.f);
                *(float2*)(Hs + rl * AS_STRIDE + col) = v;
            }
        }
    }
    __syncthreads();
    if (!first) {
        float cs[8], cq[8];
#pragma unroll
        for (int j = 0; j < 8; j++) { cs[j] = 0.f; cq[j] = 0.f; }
#pragma unroll
        for (int i = 0; i < 8; i++) {
            int rl = rg * 8 + i;
            int row = rowbase + rl;
            if (row < N) {
#pragma unroll
                for (int j = 0; j < 4; j++) {
                    float2 v = unpack2(acc[i][j]);
                    int col = cg * 8 + 2 * j;
                    v.x = fmaxf(v.x + rbsm[col], 0.f) + Hs[rl * AS_STRIDE + col];
                    v.y = fmaxf(v.y + rbsm[col + 1], 0.f) + Hs[rl * AS_STRIDE + col + 1];
                    *(float2*)(g_h + row * D + col) = v;
                    cs[2 * j]     += v.x;  cq[2 * j]     += v.x * v.x;
                    cs[2 * j + 1] += v.y;  cq[2 * j + 1] += v.y * v.y;
                }
            }
        }
#pragma unroll
        for (int j = 0; j < 8; j++) {
            atomicAdd(&scs[cg * 8 + j], cs[j]);
            atomicAdd(&scq[cg * 8 + j], cq[j]);
        }
    }
    __syncthreads();
    if (tid < 128) {
        atomicAdd(&g_colsum[tid], scs[tid]);
        atomicAdd(&g_colsq[tid], scq[tid]);
    }
}

// ---------------- BN stats finalize + normalize ----------------
__global__ void stats_kernel(const float* __restrict__ gamma,
                             const float* __restrict__ beta, int N) {
    int t = threadIdx.x;
    float invN = 1.0f / (float)N;
    float mu = g_colsum[t] * invN;
    float var = g_colsq[t] * invN - mu * mu;
    var = fmaxf(var, 0.f);
    float istd = rsqrtf(var + 1e-5f);
    float sc = gamma[t] * istd;
    g_scale[t] = sc;
    g_shift[t] = beta[t] - mu * sc;
}

__global__ void normalize_kernel(int N, int is_final, float* __restrict__ out) {
    int total = N * 32;
    float* o = is_final ? out : g_x;
    for (int idx = blockIdx.x * blockDim.x + threadIdx.x; idx < total;
         idx += gridDim.x * blockDim.x) {
        int c4 = idx & 31;
        float4 v = ((const float4*)g_h)[idx];
        float4 s = ((const float4*)g_scale)[c4];
        float4 sh = ((const float4*)g_shift)[c4];
        float4 r;
        r.x = v.x * s.x + sh.x;
        r.y = v.y * s.y + sh.y;
        r.z = v.z * s.z + sh.z;
        r.w = v.w * s.w + sh.w;
        ((float4*)o)[idx] = r;
    }
}

// ---------------- launch ----------------
extern "C" void kernel_launch(void* const* d_in, const int* in_sizes, int n_in,
                              void* d_out, int out_size) {
    const int*   node_ids = (const int*)d_in[0];
    const int*   src      = (const int*)d_in[1];
    const int*   dst      = (const int*)d_in[2];
    const float* emb      = (const float*)d_in[3];
    const float* Ws       = (const float*)d_in[4];
    const float* bs       = (const float*)d_in[5];
    const float* Rws      = (const float*)d_in[6];
    const float* Rbs      = (const float*)d_in[7];
    const float* gammas   = (const float*)d_in[8];
    const float* betas    = (const float*)d_in[9];

    const int N = in_sizes[0];
    const int E = in_sizes[1];
    const int L = in_sizes[4] / (D * D);
    const int nch = (N + 255) / 256;

    cudaFuncSetAttribute(gemm_kernel,
                         cudaFuncAttributeMaxDynamicSharedMemorySize,
                         SMEM_BYTES);

    // --- prep: degrees, norms, CSR build, embedding gather ---
    zero_deg_kernel<<<(N + 255) / 256, 256>>>(N);
    deg_kernel<<<(E + 255) / 256, 256>>>(src, dst, E);
    finalize_norms_kernel<<<(N + 255) / 256, 256>>>(N);
    scan1_kernel<<<nch, 256>>>(N);
    scan2_kernel<<<1, 256>>>(nch);
    scan3_kernel<<<nch, 256>>>(N, E);
    fill_kernel<<<(E + 255) / 256, 256>>>(src, dst, E);
    gather_kernel<<<(N * 32 + 255) / 256, 256>>>(node_ids, emb, N);

    // --- layers ---
    for (int l = 0; l < L; ++l) {
        gather_agg_kernel<<<(N * 32 + 255) / 256, 256>>>(N);
        gemm_kernel<<<(N + 63) / 64, 256, SMEM_BYTES>>>(
            Ws + l * D * D, Rws + l * D * D, bs + l * D, Rbs + l * D, N);
        stats_kernel<<<1, 128>>>(gammas + l * D, betas + l * D, N);
        normalize_kernel<<<512, 256>>>(N, (l == L - 1) ? 1 : 0, (float*)d_out);
    }
}